// round 10
// baseline (speedup 1.0000x reference)
#include <cuda_runtime.h>
#include <cuda_fp16.h>
#include <cuda_fp8.h>
#include <cstdint>

#define NE 8
#define NH 2048
#define NI 5632
#define NT 256
#define NG 128

// ---------------- scratch (zero-init device globals; alloc-free) ----------------
__device__ int    g_count[NE];
__device__ int    g_ptok[NE * NT];
__device__ float  g_pgate[NE * NT];
__device__ __align__(256) __half g_act1[(size_t)NE * NT * NH];
__device__ __align__(256) __half g_act2[(size_t)NE * NT * NI];

// clip(x/s, ±448) -> e4m3 (RN, satfinite) -> dequant (exact in fp16)
__device__ __forceinline__ __half qdq_h(float x, float s) {
    float y = x / s;
    y = fminf(fmaxf(y, -448.f), 448.f);
    __nv_fp8_storage_t q = __nv_cvt_float_to_fp8(y, __NV_SATFINITE, __NV_E4M3);
    __half_raw hr = __nv_cvt_fp8_to_halfraw(q, __NV_E4M3);
    return *reinterpret_cast<__half*>(&hr);
}

// ---------------- kernel 1: routing (softmax top-2, per-expert token lists) ----------------
__global__ void routing_kernel(const float* __restrict__ logits) {
    int t = threadIdx.x;
    if (t < NE) g_count[t] = 0;
    __syncthreads();
    float l[NE];
#pragma unroll
    for (int i = 0; i < NE; i++) l[i] = logits[t * NE + i];
    int i0 = 0;
#pragma unroll
    for (int i = 1; i < NE; i++) if (l[i] > l[i0]) i0 = i;
    int i1 = (i0 == 0) ? 1 : 0;
#pragma unroll
    for (int i = 0; i < NE; i++) if (i != i0 && l[i] > l[i1]) i1 = i;
    float e1 = expf(l[i1] - l[i0]);
    float w0 = 1.f / (1.f + e1);
    float w1 = e1 / (1.f + e1);
    int p0 = atomicAdd(&g_count[i0], 1);
    g_ptok[i0 * NT + p0] = t; g_pgate[i0 * NT + p0] = w0;
    int p1 = atomicAdd(&g_count[i1], 1);
    g_ptok[i1 * NT + p1] = t; g_pgate[i1 * NT + p1] = w1;
}

// ---------------- kernel 2: gather + qdq(s1) ----------------
__global__ void act1_kernel(const float* __restrict__ hidden, const float* __restrict__ s1v) {
    int b = blockIdx.x;
    int e = b >> 8, pos = b & 255;
    if (pos >= g_count[e]) return;       // padded rows stay zero
    int t = g_ptok[b];
    float s1 = s1v[e];
    const float* src = hidden + (size_t)t * NH;
    __half* dst = g_act1 + (size_t)b * NH;
    for (int j = threadIdx.x; j < NH; j += blockDim.x)
        dst[j] = qdq_h(src[j], s1);
}

// ---------------- SIMT GEMM1: weights are INT32 ----------------
// 256 thr: q=tid&15 -> 4 cols (n0+4q..+3), s=tid>>4 -> 4 rows (4s..4s+3)
__global__ void __launch_bounds__(256) gemm1_simt(
    const int* __restrict__ w1, const float* __restrict__ w1s,
    const float* __restrict__ s1v, const float* __restrict__ s2v)
{
    __shared__ __half acts[NG][64];
    const int e = blockIdx.y, n0 = blockIdx.x * 64;
    const int cnt = g_count[e];
    const int tid = threadIdx.x, q = tid & 15, s = tid >> 4;
    const int n = n0 + q * 4;
    const float s1 = s1v[e], s2 = s2v[e];
    const int* wu0 = w1 + (size_t)e * NH * (2 * NI) + n;
    const int* wg0 = wu0 + NI;
    const float* su0 = w1s + (size_t)e * (NH / NG) * (2 * NI) + n;
    const float* sg0 = su0 + NI;

    for (int m0 = 0; m0 < cnt; m0 += 64) {
        float aU[4][4] = {}, aG[4][4] = {};
        for (int kb = 0; kb < NH; kb += NG) {
            __syncthreads();
#pragma unroll
            for (int it = 0; it < 4; it++) {           // 64 rows x 128 k, transposed
                int lin = tid + it * 256;
                int row = lin & 63, cc = lin >> 6;
                uint4 v = *(const uint4*)(g_act1 + (size_t)(e * NT + m0 + row) * NH + kb + cc * 8);
                const __half* hv = (const __half*)&v;
#pragma unroll
                for (int j = 0; j < 8; j++) acts[cc * 8 + j][row] = hv[j];
            }
            __syncthreads();
            float rU[4][4] = {}, rG[4][4] = {};
            const int* pu = wu0 + (size_t)kb * (2 * NI);
            const int* pg = wg0 + (size_t)kb * (2 * NI);
#pragma unroll 4
            for (int kk = 0; kk < NG; kk++) {
                int4 wu = *(const int4*)pu; pu += 2 * NI;
                int4 wg = *(const int4*)pg; pg += 2 * NI;
                uint2 av = *(const uint2*)&acts[kk][s * 4];
                float2 a01 = __half22float2(*(const __half2*)&av.x);
                float2 a23 = __half22float2(*(const __half2*)&av.y);
                float a[4]  = { a01.x, a01.y, a23.x, a23.y };
                float fu[4] = { (float)wu.x, (float)wu.y, (float)wu.z, (float)wu.w };
                float fg[4] = { (float)wg.x, (float)wg.y, (float)wg.z, (float)wg.w };
#pragma unroll
                for (int i = 0; i < 4; i++)
#pragma unroll
                    for (int j = 0; j < 4; j++) {
                        rU[i][j] += a[i] * fu[j];
                        rG[i][j] += a[i] * fg[j];
                    }
            }
            const int g = kb >> 7;
            const float4 sU4 = *(const float4*)(su0 + (size_t)g * (2 * NI));
            const float4 sG4 = *(const float4*)(sg0 + (size_t)g * (2 * NI));
            const float su[4] = { sU4.x, sU4.y, sU4.z, sU4.w };
            const float sg[4] = { sG4.x, sG4.y, sG4.z, sG4.w };
#pragma unroll
            for (int i = 0; i < 4; i++)
#pragma unroll
                for (int j = 0; j < 4; j++) {
                    aU[i][j] += rU[i][j] * su[j];
                    aG[i][j] += rG[i][j] * sg[j];
                }
        }
        // epilogue: fc1=acc*s1; h = up * silu(gate) (gate = 2nd half); qdq(s2)
#pragma unroll
        for (int i = 0; i < 4; i++) {
            int m = m0 + s * 4 + i;
            if (m >= cnt) continue;
            __half* orow = g_act2 + (size_t)(e * NT + m) * NI + n;
#pragma unroll
            for (int j = 0; j < 4; j++) {
                float u  = aU[i][j] * s1;
                float gg = aG[i][j] * s1;
                float h = u * gg / (1.f + expf(-gg));
                orow[j] = qdq_h(h, s2);
            }
        }
    }
}

// ---------------- SIMT GEMM2 (int32 weights) + gated scatter ----------------
__global__ void __launch_bounds__(256) gemm2_simt(
    const int* __restrict__ w2, const float* __restrict__ w2s,
    const float* __restrict__ s2v, float* __restrict__ out)
{
    __shared__ __half acts[NG][64];
    const int e = blockIdx.y, n0 = blockIdx.x * 64;
    const int cnt = g_count[e];
    const int tid = threadIdx.x, q = tid & 15, s = tid >> 4;
    const int n = n0 + q * 4;
    const int* w0  = w2 + (size_t)e * NI * NH + n;
    const float* sc0 = w2s + (size_t)e * (NI / NG) * NH + n;

    for (int m0 = 0; m0 < cnt; m0 += 64) {
        float ac[4][4] = {};
        for (int kb = 0; kb < NI; kb += NG) {
            __syncthreads();
#pragma unroll
            for (int it = 0; it < 4; it++) {
                int lin = tid + it * 256;
                int row = lin & 63, cc = lin >> 6;
                uint4 v = *(const uint4*)(g_act2 + (size_t)(e * NT + m0 + row) * NI + kb + cc * 8);
                const __half* hv = (const __half*)&v;
#pragma unroll
                for (int j = 0; j < 8; j++) acts[cc * 8 + j][row] = hv[j];
            }
            __syncthreads();
            float r[4][4] = {};
            const int* p = w0 + (size_t)kb * NH;
#pragma unroll 4
            for (int kk = 0; kk < NG; kk++) {
                int4 w = *(const int4*)p; p += NH;
                uint2 av = *(const uint2*)&acts[kk][s * 4];
                float2 a01 = __half22float2(*(const __half2*)&av.x);
                float2 a23 = __half22float2(*(const __half2*)&av.y);
                float a[4]  = { a01.x, a01.y, a23.x, a23.y };
                float fw[4] = { (float)w.x, (float)w.y, (float)w.z, (float)w.w };
#pragma unroll
                for (int i = 0; i < 4; i++)
#pragma unroll
                    for (int j = 0; j < 4; j++)
                        r[i][j] += a[i] * fw[j];
            }
            const int g = kb >> 7;
            const float4 sw4 = *(const float4*)(sc0 + (size_t)g * NH);
            const float sw[4] = { sw4.x, sw4.y, sw4.z, sw4.w };
#pragma unroll
            for (int i = 0; i < 4; i++)
#pragma unroll
                for (int j = 0; j < 4; j++)
                    ac[i][j] += r[i][j] * sw[j];
        }
        const float s2 = s2v[e];
#pragma unroll
        for (int i = 0; i < 4; i++) {
            int m = m0 + s * 4 + i;
            if (m >= cnt) continue;
            int tok = g_ptok[e * NT + m];
            float wgt = g_pgate[e * NT + m] * s2;
            float* od = out + (size_t)tok * NH + n;
#pragma unroll
            for (int j = 0; j < 4; j++)
                atomicAdd(od + j, ac[i][j] * wgt);
        }
    }
}

// ---------------- launch: bind inputs by element count ----------------
extern "C" void kernel_launch(void* const* d_in, const int* in_sizes, int n_in,
                              void* d_out, int out_size) {
    const float* hidden = nullptr;
    const float* logits = nullptr;
    const int*   w1     = nullptr;   // int32 quantized weights
    const int*   w2     = nullptr;   // int32 quantized weights
    const float* w1s    = nullptr;
    const float* w2s    = nullptr;
    const float* s1     = nullptr;
    const float* s2     = nullptr;

    for (int i = 0; i < n_in; i++) {
        switch (in_sizes[i]) {
            case 524288:    hidden = (const float*)d_in[i]; break;
            case 2048:      logits = (const float*)d_in[i]; break;
            case 184549376: w1     = (const int*)d_in[i];   break;
            case 92274688:  w2     = (const int*)d_in[i];   break;
            case 1441792:   w1s    = (const float*)d_in[i]; break;
            case 720896:    w2s    = (const float*)d_in[i]; break;
            case 8:
                if (!s1) s1 = (const float*)d_in[i];
                else     s2 = (const float*)d_in[i];
                break;
            default: break;
        }
    }
    float* out = (float*)d_out;

    cudaMemsetAsync(out, 0, (size_t)out_size * sizeof(float));
    routing_kernel<<<1, NT>>>(logits);
    act1_kernel<<<NE * NT, 256>>>(hidden, s1);
    gemm1_simt<<<dim3(NI / 64, NE), 256>>>(w1, w1s, s1, s2);
    gemm2_simt<<<dim3(NH / 64, NE), 256>>>(w2, w2s, s2, out);
}

// round 12
// speedup vs baseline: 8.7047x; 8.7047x over previous
#include <cuda_runtime.h>
#include <cuda_fp16.h>
#include <cuda_fp8.h>
#include <cstdint>

#define NE 8
#define NH 2048
#define NI 5632
#define NT 256
#define NG 128

// ---------------- scratch (zero-init device globals; alloc-free) ----------------
__device__ int    g_count[NE];
__device__ int    g_ptok[NE * NT];
__device__ float  g_pgate[NE * NT];
__device__ __align__(256) __half g_act1[(size_t)NE * NT * NH];
__device__ __align__(256) __half g_act2[(size_t)NE * NT * NI];

// ---------------- helpers ----------------
__device__ __forceinline__ uint32_t smem_u32(const void* p) {
    return (uint32_t)__cvta_generic_to_shared(p);
}
__device__ __forceinline__ void ldsm_x4(uint32_t* r, uint32_t addr) {
    asm volatile("ldmatrix.sync.aligned.m8n8.x4.shared.b16 {%0,%1,%2,%3}, [%4];\n"
                 : "=r"(r[0]), "=r"(r[1]), "=r"(r[2]), "=r"(r[3]) : "r"(addr));
}
__device__ __forceinline__ void ldsm_x4_t(uint32_t* r, uint32_t addr) {
    asm volatile("ldmatrix.sync.aligned.m8n8.x4.trans.shared.b16 {%0,%1,%2,%3}, [%4];\n"
                 : "=r"(r[0]), "=r"(r[1]), "=r"(r[2]), "=r"(r[3]) : "r"(addr));
}
__device__ __forceinline__ void mma16816(float* d, const uint32_t* a, const uint32_t* b) {
    asm volatile("mma.sync.aligned.m16n8k16.row.col.f32.f16.f16.f32 "
                 "{%0,%1,%2,%3}, {%4,%5,%6,%7}, {%8,%9}, {%0,%1,%2,%3};\n"
                 : "+f"(d[0]), "+f"(d[1]), "+f"(d[2]), "+f"(d[3])
                 : "r"(a[0]), "r"(a[1]), "r"(a[2]), "r"(a[3]), "r"(b[0]), "r"(b[1]));
}
// clip(x/s, ±448) -> e4m3 (RN, satfinite) -> dequant (exact in fp16)
__device__ __forceinline__ __half qdq_h(float x, float s) {
    float y = x / s;
    y = fminf(fmaxf(y, -448.f), 448.f);
    __nv_fp8_storage_t q = __nv_cvt_float_to_fp8(y, __NV_SATFINITE, __NV_E4M3);
    __half_raw hr = __nv_cvt_fp8_to_halfraw(q, __NV_E4M3);
    return *reinterpret_cast<__half*>(&hr);
}

// ---------------- kernel 1: routing ----------------
__global__ void routing_kernel(const float* __restrict__ logits) {
    int t = threadIdx.x;
    if (t < NE) g_count[t] = 0;
    __syncthreads();
    float l[NE];
#pragma unroll
    for (int i = 0; i < NE; i++) l[i] = logits[t * NE + i];
    int i0 = 0;
#pragma unroll
    for (int i = 1; i < NE; i++) if (l[i] > l[i0]) i0 = i;
    int i1 = (i0 == 0) ? 1 : 0;
#pragma unroll
    for (int i = 0; i < NE; i++) if (i != i0 && l[i] > l[i1]) i1 = i;
    float e1 = expf(l[i1] - l[i0]);
    float w0 = 1.f / (1.f + e1);
    float w1 = e1 / (1.f + e1);
    int p0 = atomicAdd(&g_count[i0], 1);
    g_ptok[i0 * NT + p0] = t; g_pgate[i0 * NT + p0] = w0;
    int p1 = atomicAdd(&g_count[i1], 1);
    g_ptok[i1 * NT + p1] = t; g_pgate[i1 * NT + p1] = w1;
}

// ---------------- kernel 2: gather + qdq(s1) ----------------
__global__ void act1_kernel(const float* __restrict__ hidden, const float* __restrict__ s1v) {
    int b = blockIdx.x;
    int e = b >> 8, pos = b & 255;
    if (pos >= g_count[e]) return;       // padded rows stay zero
    int t = g_ptok[b];
    float s1 = s1v[e];
    const float* src = hidden + (size_t)t * NH;
    __half* dst = g_act1 + (size_t)b * NH;
    for (int j = threadIdx.x; j < NH; j += blockDim.x)
        dst[j] = qdq_h(src[j], s1);
}

// ---------------- GEMM tiling config ----------------
#define BM 128
#define BK 32
#define BN 64            // per half for GEMM1; total for GEMM2
#define WA (BK + 8)
#define WB (BN + 8)

// ---------------- kernel 3: mma GEMM1, integer-fp16 weights + per-group scale fold ----------------
__global__ void __launch_bounds__(256) gemm1_kernel(
    const int* __restrict__ w1, const float* __restrict__ w1s,
    const float* __restrict__ s1v, const float* __restrict__ s2v)
{
    __shared__ __align__(16) __half As[BM][WA];
    __shared__ __align__(16) __half Bu[BK][WB];
    __shared__ __align__(16) __half Bg[BK][WB];

    int e = blockIdx.z, mt = blockIdx.y, nb = blockIdx.x;
    int cnt = g_count[e];
    int m0 = mt * BM;
    if (m0 >= cnt) return;

    int tid = threadIdx.x, lane = tid & 31, wid = tid >> 5;
    int mw = wid >> 1, nw = wid & 1;

    float mU[2][4][4], mG[2][4][4];      // scaled masters
    float gU[2][4][4], gG[2][4][4];      // per-group integer accumulators
#pragma unroll
    for (int a = 0; a < 2; a++)
#pragma unroll
        for (int b = 0; b < 4; b++)
#pragma unroll
            for (int c = 0; c < 4; c++) {
                mU[a][b][c] = 0.f; mG[a][b][c] = 0.f;
                gU[a][b][c] = 0.f; gG[a][b][c] = 0.f;
            }

    const int n0 = nb * BN;
    const float s1 = s1v[e], s2 = s2v[e];

    // B-loader mapping: 16 ints per thread per k-tile
    const int bt_tile = tid >> 7;
    const int bt_r    = (tid >> 2) & 31;
    const int bt_c    = tid & 3;
    const int* wbase = w1 + (size_t)e * NH * (2 * NI) + (size_t)bt_r * (2 * NI)
                     + (bt_tile ? NI : 0) + n0 + bt_c * 16;
    __half* bs_dst = bt_tile ? &Bg[bt_r][bt_c * 16] : &Bu[bt_r][bt_c * 16];
    const __half* a_src = g_act1 + (size_t)(e * NT + m0) * NH;

    // per-thread scale base for fold: columns nj*8 + parity at (n0 + nw*32 + (lane&3)*2)
    const float* sFu = w1s + (size_t)e * (NH / NG) * (2 * NI) + n0 + nw * 32 + (lane & 3) * 2;
    const float* sFg = sFu + NI;

    for (int kt = 0; kt < NH / BK; kt++) {
        const int k0 = kt * BK;
#pragma unroll
        for (int i = 0; i < 4; i++) {
            int lin = tid + i * 256;
            int row = lin >> 3, cg = lin & 7;
            uint2 v = *(const uint2*)(a_src + (size_t)row * NH + k0 + cg * 4);
            *(uint2*)&As[row][cg * 4] = v;
        }
        // B: raw integer weights -> fp16 (exact), no scale
        {
            const int4* wp = (const int4*)(wbase + (size_t)k0 * (2 * NI));
            int4 wv[4] = { wp[0], wp[1], wp[2], wp[3] };
            const int* wi = (const int*)wv;
            __align__(16) __half h[16];
#pragma unroll
            for (int j = 0; j < 16; j++) h[j] = __int2half_rn(wi[j]);
            uint4* d = (uint4*)bs_dst;
            d[0] = *(uint4*)&h[0];
            d[1] = *(uint4*)&h[8];
        }
        __syncthreads();
#pragma unroll
        for (int ks = 0; ks < 2; ks++) {
            uint32_t a[2][4], bu[2][4], bg[2][4];
#pragma unroll
            for (int mi = 0; mi < 2; mi++)
                ldsm_x4(a[mi], smem_u32(&As[mw * 32 + mi * 16 + (lane & 15)][ks * 16 + (lane >> 4) * 8]));
#pragma unroll
            for (int nj2 = 0; nj2 < 2; nj2++) {
                ldsm_x4_t(bu[nj2], smem_u32(&Bu[ks * 16 + (lane & 15)][nw * 32 + nj2 * 16 + (lane >> 4) * 8]));
                ldsm_x4_t(bg[nj2], smem_u32(&Bg[ks * 16 + (lane & 15)][nw * 32 + nj2 * 16 + (lane >> 4) * 8]));
            }
#pragma unroll
            for (int mi = 0; mi < 2; mi++)
#pragma unroll
                for (int nj = 0; nj < 4; nj++) {
                    mma16816(gU[mi][nj], a[mi], &bu[nj >> 1][(nj & 1) * 2]);
                    mma16816(gG[mi][nj], a[mi], &bg[nj >> 1][(nj & 1) * 2]);
                }
        }
        __syncthreads();
        // fold group accumulators with per-(group,col) scales every NG k
        if ((kt & 3) == 3) {
            const int g = kt >> 2;
#pragma unroll
            for (int nj = 0; nj < 4; nj++) {
                float2 su2 = *(const float2*)(sFu + (size_t)g * (2 * NI) + nj * 8);
                float2 sg2 = *(const float2*)(sFg + (size_t)g * (2 * NI) + nj * 8);
#pragma unroll
                for (int mi = 0; mi < 2; mi++) {
                    mU[mi][nj][0] += gU[mi][nj][0] * su2.x;
                    mU[mi][nj][1] += gU[mi][nj][1] * su2.y;
                    mU[mi][nj][2] += gU[mi][nj][2] * su2.x;
                    mU[mi][nj][3] += gU[mi][nj][3] * su2.y;
                    mG[mi][nj][0] += gG[mi][nj][0] * sg2.x;
                    mG[mi][nj][1] += gG[mi][nj][1] * sg2.y;
                    mG[mi][nj][2] += gG[mi][nj][2] * sg2.x;
                    mG[mi][nj][3] += gG[mi][nj][3] * sg2.y;
                    gU[mi][nj][0] = 0.f; gU[mi][nj][1] = 0.f;
                    gU[mi][nj][2] = 0.f; gU[mi][nj][3] = 0.f;
                    gG[mi][nj][0] = 0.f; gG[mi][nj][1] = 0.f;
                    gG[mi][nj][2] = 0.f; gG[mi][nj][3] = 0.f;
                }
            }
        }
    }

    // epilogue: fc1 = m*s1; h = up*silu(gate); act2 = qdq(h, s2)
#pragma unroll
    for (int mi = 0; mi < 2; mi++) {
#pragma unroll
        for (int h8 = 0; h8 < 2; h8++) {
            int row = mw * 32 + mi * 16 + (lane >> 2) + h8 * 8;
            int m = m0 + row;
            if (m >= cnt) continue;
            __half* orow = g_act2 + (size_t)(e * NT + m) * NI + n0;
#pragma unroll
            for (int nj = 0; nj < 4; nj++) {
                int col = nw * 32 + nj * 8 + (lane & 3) * 2;
                float u0 = mU[mi][nj][h8 * 2 + 0] * s1;
                float u1 = mU[mi][nj][h8 * 2 + 1] * s1;
                float g0 = mG[mi][nj][h8 * 2 + 0] * s1;
                float g1 = mG[mi][nj][h8 * 2 + 1] * s1;
                float h0 = u0 * g0 / (1.f + expf(-g0));
                float h1 = u1 * g1 / (1.f + expf(-g1));
                __half2 hq;
                hq.x = qdq_h(h0, s2);
                hq.y = qdq_h(h1, s2);
                *(__half2*)(orow + col) = hq;
            }
        }
    }
}

// ---------------- kernel 4: mma GEMM2, integer-fp16 weights + group fold + scatter ----------------
__global__ void __launch_bounds__(256) gemm2_kernel(
    const int* __restrict__ w2, const float* __restrict__ w2s,
    const float* __restrict__ s2v, float* __restrict__ out)
{
    __shared__ __align__(16) __half As[BM][WA];
    __shared__ __align__(16) __half Bs[BK][WB];

    int e = blockIdx.z, mt = blockIdx.y, nb = blockIdx.x;
    int cnt = g_count[e];
    int m0 = mt * BM;
    if (m0 >= cnt) return;

    int tid = threadIdx.x, lane = tid & 31, wid = tid >> 5;
    int mw = wid >> 1, nw = wid & 1;

    float mA[2][4][4], gA[2][4][4];
#pragma unroll
    for (int a = 0; a < 2; a++)
#pragma unroll
        for (int b = 0; b < 4; b++)
#pragma unroll
            for (int c = 0; c < 4; c++) { mA[a][b][c] = 0.f; gA[a][b][c] = 0.f; }

    const int n0 = nb * BN;
    const int b_r = tid >> 3;
    const int b_c = tid & 7;
    const int* wbase = w2 + (size_t)e * NI * NH + (size_t)b_r * NH + n0 + b_c * 8;
    const __half* a_src = g_act2 + (size_t)(e * NT + m0) * NI;
    const float* sF = w2s + (size_t)e * (NI / NG) * NH + n0 + nw * 32 + (lane & 3) * 2;

    for (int kt = 0; kt < NI / BK; kt++) {
        const int k0 = kt * BK;
#pragma unroll
        for (int i = 0; i < 4; i++) {
            int lin = tid + i * 256;
            int row = lin >> 3, cg = lin & 7;
            uint2 v = *(const uint2*)(a_src + (size_t)row * NI + k0 + cg * 4);
            *(uint2*)&As[row][cg * 4] = v;
        }
        {
            const int4* wp = (const int4*)(wbase + (size_t)k0 * NH);
            int4 wv[2] = { wp[0], wp[1] };
            const int* wi = (const int*)wv;
            __align__(16) __half h[8];
#pragma unroll
            for (int j = 0; j < 8; j++) h[j] = __int2half_rn(wi[j]);
            *(uint4*)&Bs[b_r][b_c * 8] = *(uint4*)h;
        }
        __syncthreads();
#pragma unroll
        for (int ks = 0; ks < 2; ks++) {
            uint32_t a[2][4], bf[2][4];
#pragma unroll
            for (int mi = 0; mi < 2; mi++)
                ldsm_x4(a[mi], smem_u32(&As[mw * 32 + mi * 16 + (lane & 15)][ks * 16 + (lane >> 4) * 8]));
#pragma unroll
            for (int nj2 = 0; nj2 < 2; nj2++)
                ldsm_x4_t(bf[nj2], smem_u32(&Bs[ks * 16 + (lane & 15)][nw * 32 + nj2 * 16 + (lane >> 4) * 8]));
#pragma unroll
            for (int mi = 0; mi < 2; mi++)
#pragma unroll
                for (int nj = 0; nj < 4; nj++)
                    mma16816(gA[mi][nj], a[mi], &bf[nj >> 1][(nj & 1) * 2]);
        }
        __syncthreads();
        if ((kt & 3) == 3) {
            const int g = kt >> 2;
#pragma unroll
            for (int nj = 0; nj < 4; nj++) {
                float2 sw2 = *(const float2*)(sF + (size_t)g * NH + nj * 8);
#pragma unroll
                for (int mi = 0; mi < 2; mi++) {
                    mA[mi][nj][0] += gA[mi][nj][0] * sw2.x;
                    mA[mi][nj][1] += gA[mi][nj][1] * sw2.y;
                    mA[mi][nj][2] += gA[mi][nj][2] * sw2.x;
                    mA[mi][nj][3] += gA[mi][nj][3] * sw2.y;
                    gA[mi][nj][0] = 0.f; gA[mi][nj][1] = 0.f;
                    gA[mi][nj][2] = 0.f; gA[mi][nj][3] = 0.f;
                }
            }
        }
    }

    const float s2 = s2v[e];
#pragma unroll
    for (int mi = 0; mi < 2; mi++) {
#pragma unroll
        for (int h8 = 0; h8 < 2; h8++) {
            int row = mw * 32 + mi * 16 + (lane >> 2) + h8 * 8;
            int m = m0 + row;
            if (m >= cnt) continue;
            int tok = g_ptok[e * NT + m];
            float wgt = g_pgate[e * NT + m] * s2;
            float* od = out + (size_t)tok * NH + n0;
#pragma unroll
            for (int nj = 0; nj < 4; nj++) {
                int col = nw * 32 + nj * 8 + (lane & 3) * 2;
                atomicAdd(od + col,     mA[mi][nj][h8 * 2 + 0] * wgt);
                atomicAdd(od + col + 1, mA[mi][nj][h8 * 2 + 1] * wgt);
            }
        }
    }
}

// ---------------- launch ----------------
extern "C" void kernel_launch(void* const* d_in, const int* in_sizes, int n_in,
                              void* d_out, int out_size) {
    const float* hidden = nullptr;
    const float* logits = nullptr;
    const int*   w1     = nullptr;
    const int*   w2     = nullptr;
    const float* w1s    = nullptr;
    const float* w2s    = nullptr;
    const float* s1     = nullptr;
    const float* s2     = nullptr;

    for (int i = 0; i < n_in; i++) {
        switch (in_sizes[i]) {
            case 524288:    hidden = (const float*)d_in[i]; break;
            case 2048:      logits = (const float*)d_in[i]; break;
            case 184549376: w1     = (const int*)d_in[i];   break;
            case 92274688:  w2     = (const int*)d_in[i];   break;
            case 1441792:   w1s    = (const float*)d_in[i]; break;
            case 720896:    w2s    = (const float*)d_in[i]; break;
            case 8:
                if (!s1) s1 = (const float*)d_in[i];
                else     s2 = (const float*)d_in[i];
                break;
            default: break;
        }
    }
    float* out = (float*)d_out;

    cudaMemsetAsync(out, 0, (size_t)out_size * sizeof(float));
    routing_kernel<<<1, NT>>>(logits);
    act1_kernel<<<NE * NT, 256>>>(hidden, s1);
    gemm1_kernel<<<dim3(NI / BN, 2, NE), 256>>>(w1, w1s, s1, s2);
    gemm2_kernel<<<dim3(NH / BN, 2, NE), 256>>>(w2, w2s, s2, out);
}

// round 15
// speedup vs baseline: 12.5571x; 1.4426x over previous
#include <cuda_runtime.h>
#include <cuda_fp16.h>
#include <cuda_fp8.h>
#include <cstdint>

#define NE 8
#define NH 2048
#define NI 5632
#define NT 256
#define NG 128

#define BM 128
#define BN 64
#define BK 32
#define WA 40          // As row stride (halfs): 80B
#define WB 72          // Bs row stride (halfs): 144B

// ---------------- scratch (zero-init device globals; alloc-free) ----------------
__device__ int    g_count[NE];
__device__ int    g_ptok[NE * NT];
__device__ float  g_pgate[NE * NT];
__device__ __align__(256) __half g_act1[(size_t)NE * NT * NH];
__device__ __align__(256) __half g_act2[(size_t)NE * NT * NI];
__device__ __align__(256) float  g_fc1[(size_t)NE * NT * 2 * NI];

// ---------------- helpers ----------------
__device__ __forceinline__ uint32_t smem_u32(const void* p) {
    return (uint32_t)__cvta_generic_to_shared(p);
}
__device__ __forceinline__ void ldsm_x4(uint32_t* r, uint32_t addr) {
    asm volatile("ldmatrix.sync.aligned.m8n8.x4.shared.b16 {%0,%1,%2,%3}, [%4];\n"
                 : "=r"(r[0]), "=r"(r[1]), "=r"(r[2]), "=r"(r[3]) : "r"(addr));
}
__device__ __forceinline__ void ldsm_x4_t(uint32_t* r, uint32_t addr) {
    asm volatile("ldmatrix.sync.aligned.m8n8.x4.trans.shared.b16 {%0,%1,%2,%3}, [%4];\n"
                 : "=r"(r[0]), "=r"(r[1]), "=r"(r[2]), "=r"(r[3]) : "r"(addr));
}
__device__ __forceinline__ void mma16816(float* d, const uint32_t* a, const uint32_t* b) {
    asm volatile("mma.sync.aligned.m16n8k16.row.col.f32.f16.f16.f32 "
                 "{%0,%1,%2,%3}, {%4,%5,%6,%7}, {%8,%9}, {%0,%1,%2,%3};\n"
                 : "+f"(d[0]), "+f"(d[1]), "+f"(d[2]), "+f"(d[3])
                 : "r"(a[0]), "r"(a[1]), "r"(a[2]), "r"(a[3]), "r"(b[0]), "r"(b[1]));
}
__device__ __forceinline__ void cp16(uint32_t dst, const void* src) {
    asm volatile("cp.async.cg.shared.global [%0], [%1], 16;\n" :: "r"(dst), "l"(src));
}
#define CP_COMMIT asm volatile("cp.async.commit_group;\n" ::)
#define CP_WAIT0  asm volatile("cp.async.wait_group 0;\n" ::)

// clip(x/s, ±448) -> e4m3 (RN, satfinite) -> dequant (exact in fp16)
__device__ __forceinline__ __half qdq_h(float x, float s) {
    float y = x / s;
    y = fminf(fmaxf(y, -448.f), 448.f);
    __nv_fp8_storage_t q = __nv_cvt_float_to_fp8(y, __NV_SATFINITE, __NV_E4M3);
    __half_raw hr = __nv_cvt_fp8_to_halfraw(q, __NV_E4M3);
    return *reinterpret_cast<__half*>(&hr);
}

// ---------------- kernel 1: routing ----------------
__global__ void routing_kernel(const float* __restrict__ logits) {
    int t = threadIdx.x;
    if (t < NE) g_count[t] = 0;
    __syncthreads();
    float l[NE];
#pragma unroll
    for (int i = 0; i < NE; i++) l[i] = logits[t * NE + i];
    int i0 = 0;
#pragma unroll
    for (int i = 1; i < NE; i++) if (l[i] > l[i0]) i0 = i;
    int i1 = (i0 == 0) ? 1 : 0;
#pragma unroll
    for (int i = 0; i < NE; i++) if (i != i0 && l[i] > l[i1]) i1 = i;
    float e1 = expf(l[i1] - l[i0]);
    float w0 = 1.f / (1.f + e1);
    float w1 = e1 / (1.f + e1);
    int p0 = atomicAdd(&g_count[i0], 1);
    g_ptok[i0 * NT + p0] = t; g_pgate[i0 * NT + p0] = w0;
    int p1 = atomicAdd(&g_count[i1], 1);
    g_ptok[i1 * NT + p1] = t; g_pgate[i1 * NT + p1] = w1;
}

// ---------------- kernel 2: gather + qdq(s1) ----------------
__global__ void act1_kernel(const float* __restrict__ hidden, const float* __restrict__ s1v) {
    int b = blockIdx.x;
    int e = b >> 8, pos = b & 255;
    if (pos >= g_count[e]) return;       // padded rows stay zero
    int t = g_ptok[b];
    float s1 = s1v[e];
    const float* src = hidden + (size_t)t * NH;
    __half* dst = g_act1 + (size_t)b * NH;
    for (int j = threadIdx.x; j < NH; j += blockDim.x)
        dst[j] = qdq_h(src[j], s1);
}

// ---------------- unified double-buffered GEMM core (static smem, 256 thr) ----------------
// W[k][n] int32 row-stride NTOT; Ws[g][n]; A fp16.
// FC1: writes fp32 to g_fc1 (device-side symbol, NOT a host-passed arg).
// !FC1: gated atomic scatter to harness out pointer.
template<int KDIM, int NTOT, bool FC1>
__global__ void __launch_bounds__(256, 2) gemm_core(
    const int* __restrict__ W, const float* __restrict__ Ws,
    float* __restrict__ outp, const float* __restrict__ s2v)
{
    constexpr int KT = KDIM / BK;
    __shared__ __align__(16) __half As[2][BM][WA];   // 20480 B
    __shared__ __align__(16) int    Br[2][BK][BN];   // 16384 B
    __shared__ __align__(16) __half Bs[2][BK][WB];   //  9216 B  (total 46080 < 48K)

    const int e = blockIdx.z, mt = blockIdx.y, nb = blockIdx.x;
    const int cnt = g_count[e];
    const int m0 = mt * BM;
    if (m0 >= cnt) return;
    const int n0 = nb * BN;
    const int tid = threadIdx.x, lane = tid & 31, wid = tid >> 5;
    const int mw = wid >> 1, nw = wid & 1;   // 4 m-warps x 2 n-warps, 32x32 warp tile

    const __half* Abase = (FC1 ? g_act1 : g_act2) + (size_t)(e * NT + m0) * KDIM;
    const int*    Wbase = W + (size_t)e * KDIM * NTOT + n0;
    const float*  sF = Ws + (size_t)e * (KDIM / NG) * NTOT + n0 + nw * 32 + (lane & 3) * 2;

    float mAcc[2][4][4], gAcc[2][4][4];
#pragma unroll
    for (int a = 0; a < 2; a++)
#pragma unroll
        for (int b = 0; b < 4; b++)
#pragma unroll
            for (int c = 0; c < 4; c++) { mAcc[a][b][c] = 0.f; gAcc[a][b][c] = 0.f; }

    auto stage = [&](int kt_, int sl) {
        const int k0 = kt_ * BK;
#pragma unroll
        for (int i = 0; i < 2; i++) {   // A: 128x32 halfs = 512 x 16B
            int ch = tid + i * 256;
            int row = ch >> 2, c = ch & 3;
            cp16(smem_u32(&As[sl][row][c * 8]), Abase + (size_t)row * KDIM + k0 + c * 8);
        }
#pragma unroll
        for (int i = 0; i < 2; i++) {   // B: 32x64 ints = 512 x 16B
            int ch = tid + i * 256;
            int row = ch >> 4, c = ch & 15;
            cp16(smem_u32(&Br[sl][row][c * 4]), Wbase + (size_t)(k0 + row) * NTOT + c * 4);
        }
    };
    auto convertB = [&](int sl) {       // 2048 ints -> fp16 (exact), 8 per thread
        int r = tid >> 3, cc = (tid & 7) * 8;
        int4 v0 = *(const int4*)&Br[sl][r][cc];
        int4 v1 = *(const int4*)&Br[sl][r][cc + 4];
        __align__(16) __half h[8];
        h[0] = __int2half_rn(v0.x); h[1] = __int2half_rn(v0.y);
        h[2] = __int2half_rn(v0.z); h[3] = __int2half_rn(v0.w);
        h[4] = __int2half_rn(v1.x); h[5] = __int2half_rn(v1.y);
        h[6] = __int2half_rn(v1.z); h[7] = __int2half_rn(v1.w);
        *(uint4*)&Bs[sl][r][cc] = *(uint4*)h;
    };
    auto mmatile = [&](int sl) {
#pragma unroll
        for (int ks = 0; ks < 2; ks++) {
            uint32_t a[2][4], bf[2][4];
#pragma unroll
            for (int mi = 0; mi < 2; mi++)
                ldsm_x4(a[mi], smem_u32(&As[sl][mw * 32 + mi * 16 + (lane & 15)][ks * 16 + (lane >> 4) * 8]));
#pragma unroll
            for (int nj2 = 0; nj2 < 2; nj2++)
                ldsm_x4_t(bf[nj2], smem_u32(&Bs[sl][ks * 16 + (lane & 15)][nw * 32 + nj2 * 16 + (lane >> 4) * 8]));
#pragma unroll
            for (int mi = 0; mi < 2; mi++)
#pragma unroll
                for (int nj = 0; nj < 4; nj++)
                    mma16816(gAcc[mi][nj], a[mi], &bf[nj >> 1][(nj & 1) * 2]);
        }
    };

    // prologue: tile 0 in, converted, visible; tile 1 in flight
    stage(0, 0); CP_COMMIT;
    CP_WAIT0; __syncthreads();       // tile0 raw visible to all
    convertB(0);
    stage(1, 1); CP_COMMIT;
    __syncthreads();                 // Bs[0] visible

    for (int kt = 0; kt < KT; kt++) {
        const int sl = kt & 1;
        mmatile(sl);
        if ((kt & 3) == 3) {         // fold group accumulators (NG = 4 k-tiles)
            const int g = kt >> 2;
#pragma unroll
            for (int nj = 0; nj < 4; nj++) {
                float2 s2_ = *(const float2*)(sF + (size_t)g * NTOT + nj * 8);
#pragma unroll
                for (int mi = 0; mi < 2; mi++) {
                    mAcc[mi][nj][0] += gAcc[mi][nj][0] * s2_.x;
                    mAcc[mi][nj][1] += gAcc[mi][nj][1] * s2_.y;
                    mAcc[mi][nj][2] += gAcc[mi][nj][2] * s2_.x;
                    mAcc[mi][nj][3] += gAcc[mi][nj][3] * s2_.y;
                    gAcc[mi][nj][0] = 0.f; gAcc[mi][nj][1] = 0.f;
                    gAcc[mi][nj][2] = 0.f; gAcc[mi][nj][3] = 0.f;
                }
            }
        }
        if (kt + 1 < KT) {
            CP_WAIT0;                // tile kt+1 arrived (this thread's copies)
            __syncthreads();         // cross-thread visibility + all done reading slot sl
            convertB(sl ^ 1);        // Bs[sl^1] <- Br[sl^1]
            if (kt + 2 < KT) { stage(kt + 2, sl); CP_COMMIT; }  // refill freed slot
            __syncthreads();         // Bs[sl^1] visible before next mmatile
        }
    }

    // epilogue
    if (FC1) {
#pragma unroll
        for (int mi = 0; mi < 2; mi++)
#pragma unroll
            for (int h8 = 0; h8 < 2; h8++) {
                int row = mw * 32 + mi * 16 + (lane >> 2) + h8 * 8;
                int m = m0 + row;
                if (m >= cnt) continue;
                // write device-global g_fc1 directly (device-side symbol reference)
                float* orow = g_fc1 + (size_t)(e * NT + m) * NTOT + n0 + nw * 32;
#pragma unroll
                for (int nj = 0; nj < 4; nj++) {
                    float2 v = make_float2(mAcc[mi][nj][h8 * 2 + 0], mAcc[mi][nj][h8 * 2 + 1]);
                    *(float2*)(orow + nj * 8 + (lane & 3) * 2) = v;
                }
            }
    } else {
        const float s2 = s2v[e];
#pragma unroll
        for (int mi = 0; mi < 2; mi++)
#pragma unroll
            for (int h8 = 0; h8 < 2; h8++) {
                int row = mw * 32 + mi * 16 + (lane >> 2) + h8 * 8;
                int m = m0 + row;
                if (m >= cnt) continue;
                int tok = g_ptok[e * NT + m];
                float wgt = g_pgate[e * NT + m] * s2;
                float* od = outp + (size_t)tok * NTOT + n0 + nw * 32;
#pragma unroll
                for (int nj = 0; nj < 4; nj++) {
                    int col = nj * 8 + (lane & 3) * 2;
                    atomicAdd(od + col,     mAcc[mi][nj][h8 * 2 + 0] * wgt);
                    atomicAdd(od + col + 1, mAcc[mi][nj][h8 * 2 + 1] * wgt);
                }
            }
    }
}

// ---------------- silu + qdq(s2): g_fc1 -> g_act2 (device symbols only) ----------------
__global__ void __launch_bounds__(256) silu_kernel(const float* __restrict__ s1v,
                                                   const float* __restrict__ s2v) {
    int b = blockIdx.x, e = b >> 8, pos = b & 255;
    if (pos >= g_count[e]) return;
    float s1 = s1v[e], s2 = s2v[e];
    const float* fr = g_fc1 + (size_t)b * (2 * NI);
    __half* orow = g_act2 + (size_t)b * NI;
    for (int j = threadIdx.x * 2; j < NI; j += 512) {
        float2 u2 = *(const float2*)(fr + j);
        float2 g2 = *(const float2*)(fr + NI + j);
        float u0 = u2.x * s1, u1 = u2.y * s1;
        float g0 = g2.x * s1, g1 = g2.y * s1;
        float h0 = u0 * g0 / (1.f + expf(-g0));
        float h1 = u1 * g1 / (1.f + expf(-g1));
        __half2 hq;
        hq.x = qdq_h(h0, s2);
        hq.y = qdq_h(h1, s2);
        *(__half2*)(orow + j) = hq;
    }
}

// ---------------- launch ----------------
extern "C" void kernel_launch(void* const* d_in, const int* in_sizes, int n_in,
                              void* d_out, int out_size) {
    const float* hidden = nullptr;
    const float* logits = nullptr;
    const int*   w1     = nullptr;
    const int*   w2     = nullptr;
    const float* w1s    = nullptr;
    const float* w2s    = nullptr;
    const float* s1     = nullptr;
    const float* s2     = nullptr;

    for (int i = 0; i < n_in; i++) {
        switch (in_sizes[i]) {
            case 524288:    hidden = (const float*)d_in[i]; break;
            case 2048:      logits = (const float*)d_in[i]; break;
            case 184549376: w1     = (const int*)d_in[i];   break;
            case 92274688:  w2     = (const int*)d_in[i];   break;
            case 1441792:   w1s    = (const float*)d_in[i]; break;
            case 720896:    w2s    = (const float*)d_in[i]; break;
            case 8:
                if (!s1) s1 = (const float*)d_in[i];
                else     s2 = (const float*)d_in[i];
                break;
            default: break;
        }
    }
    float* out = (float*)d_out;

    cudaMemsetAsync(out, 0, (size_t)out_size * sizeof(float));
    routing_kernel<<<1, NT>>>(logits);
    act1_kernel<<<NE * NT, 256>>>(hidden, s1);
    // FC1 writes g_fc1 internally (no device-symbol passed from host)
    gemm_core<NH, 2 * NI, true><<<dim3((2 * NI) / BN, 2, NE), 256>>>(w1, w1s, nullptr, nullptr);
    silu_kernel<<<NE * NT, 256>>>(s1, s2);
    gemm_core<NI, NH, false><<<dim3(NH / BN, 2, NE), 256>>>(w2, w2s, out, s2);
}

// round 16
// speedup vs baseline: 13.8429x; 1.1024x over previous
#include <cuda_runtime.h>
#include <cuda_fp16.h>
#include <cuda_fp8.h>
#include <cstdint>

#define NE 8
#define NH 2048
#define NI 5632
#define NT 256
#define NG 128

#define BM 128
#define BN 64
#define BK 32
#define WA 40          // As row stride (halfs): 80B
#define WB 72          // Bs row stride (halfs): 144B

// dynamic smem layout (3-slot rings)
#define AS_SZ (3 * BM * WA * 2)        // 30720
#define BR_SZ (3 * BK * BN * 4)        // 24576
#define BS_SZ (3 * BK * WB * 2)        // 13824
#define SMEM_TOTAL (AS_SZ + BR_SZ + BS_SZ)   // 69120

// ---------------- scratch (zero-init device globals; alloc-free) ----------------
__device__ int    g_count[NE];
__device__ int    g_ptok[NE * NT];
__device__ float  g_pgate[NE * NT];
__device__ __align__(256) __half g_act1[(size_t)NE * NT * NH];
__device__ __align__(256) __half g_act2[(size_t)NE * NT * NI];
__device__ __align__(256) float  g_fc1[(size_t)NE * NT * 2 * NI];

// ---------------- helpers ----------------
__device__ __forceinline__ uint32_t smem_u32(const void* p) {
    return (uint32_t)__cvta_generic_to_shared(p);
}
__device__ __forceinline__ void ldsm_x4(uint32_t* r, uint32_t addr) {
    asm volatile("ldmatrix.sync.aligned.m8n8.x4.shared.b16 {%0,%1,%2,%3}, [%4];\n"
                 : "=r"(r[0]), "=r"(r[1]), "=r"(r[2]), "=r"(r[3]) : "r"(addr));
}
__device__ __forceinline__ void ldsm_x4_t(uint32_t* r, uint32_t addr) {
    asm volatile("ldmatrix.sync.aligned.m8n8.x4.trans.shared.b16 {%0,%1,%2,%3}, [%4];\n"
                 : "=r"(r[0]), "=r"(r[1]), "=r"(r[2]), "=r"(r[3]) : "r"(addr));
}
__device__ __forceinline__ void mma16816(float* d, const uint32_t* a, const uint32_t* b) {
    asm volatile("mma.sync.aligned.m16n8k16.row.col.f32.f16.f16.f32 "
                 "{%0,%1,%2,%3}, {%4,%5,%6,%7}, {%8,%9}, {%0,%1,%2,%3};\n"
                 : "+f"(d[0]), "+f"(d[1]), "+f"(d[2]), "+f"(d[3])
                 : "r"(a[0]), "r"(a[1]), "r"(a[2]), "r"(a[3]), "r"(b[0]), "r"(b[1]));
}
__device__ __forceinline__ void cp16(uint32_t dst, const void* src) {
    asm volatile("cp.async.cg.shared.global [%0], [%1], 16;\n" :: "r"(dst), "l"(src));
}
#define CP_COMMIT asm volatile("cp.async.commit_group;\n" ::)
#define CP_WAIT1  asm volatile("cp.async.wait_group 1;\n" ::)
#define CP_WAIT0  asm volatile("cp.async.wait_group 0;\n" ::)

// clip(x/s, ±448) -> e4m3 (RN, satfinite) -> dequant (exact in fp16)
__device__ __forceinline__ __half qdq_h(float x, float s) {
    float y = x / s;
    y = fminf(fmaxf(y, -448.f), 448.f);
    __nv_fp8_storage_t q = __nv_cvt_float_to_fp8(y, __NV_SATFINITE, __NV_E4M3);
    __half_raw hr = __nv_cvt_fp8_to_halfraw(q, __NV_E4M3);
    return *reinterpret_cast<__half*>(&hr);
}

// ---------------- kernel 1: routing ----------------
__global__ void routing_kernel(const float* __restrict__ logits) {
    int t = threadIdx.x;
    if (t < NE) g_count[t] = 0;
    __syncthreads();
    float l[NE];
#pragma unroll
    for (int i = 0; i < NE; i++) l[i] = logits[t * NE + i];
    int i0 = 0;
#pragma unroll
    for (int i = 1; i < NE; i++) if (l[i] > l[i0]) i0 = i;
    int i1 = (i0 == 0) ? 1 : 0;
#pragma unroll
    for (int i = 0; i < NE; i++) if (i != i0 && l[i] > l[i1]) i1 = i;
    float e1 = expf(l[i1] - l[i0]);
    float w0 = 1.f / (1.f + e1);
    float w1 = e1 / (1.f + e1);
    int p0 = atomicAdd(&g_count[i0], 1);
    g_ptok[i0 * NT + p0] = t; g_pgate[i0 * NT + p0] = w0;
    int p1 = atomicAdd(&g_count[i1], 1);
    g_ptok[i1 * NT + p1] = t; g_pgate[i1 * NT + p1] = w1;
}

// ---------------- kernel 2: gather + qdq(s1) ----------------
__global__ void act1_kernel(const float* __restrict__ hidden, const float* __restrict__ s1v) {
    int b = blockIdx.x;
    int e = b >> 8, pos = b & 255;
    if (pos >= g_count[e]) return;       // padded rows stay zero
    int t = g_ptok[b];
    float s1 = s1v[e];
    const float* src = hidden + (size_t)t * NH;
    __half* dst = g_act1 + (size_t)b * NH;
    for (int j = threadIdx.x; j < NH; j += blockDim.x)
        dst[j] = qdq_h(src[j], s1);
}

// ---------------- 3-stage pipelined GEMM core (dynamic smem, 256 thr) ----------------
// W[k][n] int32 row-stride NTOT; Ws[g][n]; A fp16.
// FC1: writes fp32 to g_fc1 (device-side symbol). !FC1: gated atomic scatter to out.
template<int KDIM, int NTOT, bool FC1>
__global__ void __launch_bounds__(256, 2) gemm_core(
    const int* __restrict__ W, const float* __restrict__ Ws,
    float* __restrict__ outp, const float* __restrict__ s2v)
{
    constexpr int KT = KDIM / BK;
    extern __shared__ __align__(16) char smraw[];
    __half (*As)[BM][WA] = reinterpret_cast<__half(*)[BM][WA]>(smraw);
    int    (*Br)[BK][BN] = reinterpret_cast<int(*)[BK][BN]>(smraw + AS_SZ);
    __half (*Bs)[BK][WB] = reinterpret_cast<__half(*)[BK][WB]>(smraw + AS_SZ + BR_SZ);

    const int e = blockIdx.z, mt = blockIdx.y, nb = blockIdx.x;
    const int cnt = g_count[e];
    const int m0 = mt * BM;
    if (m0 >= cnt) return;
    const int n0 = nb * BN;
    const int tid = threadIdx.x, lane = tid & 31, wid = tid >> 5;
    const int mw = wid >> 1, nw = wid & 1;   // 4 m-warps x 2 n-warps, 32x32 warp tile

    const __half* Abase = (FC1 ? g_act1 : g_act2) + (size_t)(e * NT + m0) * KDIM;
    const int*    Wbase = W + (size_t)e * KDIM * NTOT + n0;
    const float*  sF = Ws + (size_t)e * (KDIM / NG) * NTOT + n0 + nw * 32 + (lane & 3) * 2;

    float mAcc[2][4][4], gAcc[2][4][4];
#pragma unroll
    for (int a = 0; a < 2; a++)
#pragma unroll
        for (int b = 0; b < 4; b++)
#pragma unroll
            for (int c = 0; c < 4; c++) { mAcc[a][b][c] = 0.f; gAcc[a][b][c] = 0.f; }

    // B mapping: thread owns row tid>>3, 64 ints at cols (tid&7)*8 .. +7 (2 x 16B)
    const int brow = tid >> 3, bcol = (tid & 7) * 8;

    auto stage = [&](int kt_, int sl) {
        const int k0 = kt_ * BK;
#pragma unroll
        for (int i = 0; i < 2; i++) {   // A: 128x32 halfs = 512 x 16B
            int ch = tid + i * 256;
            int row = ch >> 2, c = ch & 3;
            cp16(smem_u32(&As[sl][row][c * 8]), Abase + (size_t)row * KDIM + k0 + c * 8);
        }
#pragma unroll
        for (int i = 0; i < 2; i++)     // B: own 32B so convert needs no barrier
            cp16(smem_u32(&Br[sl][brow][bcol + i * 4]),
                 Wbase + (size_t)(k0 + brow) * NTOT + bcol + i * 4);
    };
    auto convertB = [&](int sl) {       // own data only (visible after own wait_group)
        int4 v0 = *(const int4*)&Br[sl][brow][bcol];
        int4 v1 = *(const int4*)&Br[sl][brow][bcol + 4];
        __align__(16) __half h[8];
        h[0] = __int2half_rn(v0.x); h[1] = __int2half_rn(v0.y);
        h[2] = __int2half_rn(v0.z); h[3] = __int2half_rn(v0.w);
        h[4] = __int2half_rn(v1.x); h[5] = __int2half_rn(v1.y);
        h[6] = __int2half_rn(v1.z); h[7] = __int2half_rn(v1.w);
        *(uint4*)&Bs[sl][brow][bcol] = *(uint4*)h;
    };
    auto mmatile = [&](int sl) {
#pragma unroll
        for (int ks = 0; ks < 2; ks++) {
            uint32_t a[2][4], bf[2][4];
#pragma unroll
            for (int mi = 0; mi < 2; mi++)
                ldsm_x4(a[mi], smem_u32(&As[sl][mw * 32 + mi * 16 + (lane & 15)][ks * 16 + (lane >> 4) * 8]));
#pragma unroll
            for (int nj2 = 0; nj2 < 2; nj2++)
                ldsm_x4_t(bf[nj2], smem_u32(&Bs[sl][ks * 16 + (lane & 15)][nw * 32 + nj2 * 16 + (lane >> 4) * 8]));
#pragma unroll
            for (int mi = 0; mi < 2; mi++)
#pragma unroll
                for (int nj = 0; nj < 4; nj++)
                    mma16816(gAcc[mi][nj], a[mi], &bf[nj >> 1][(nj & 1) * 2]);
        }
    };

    // prologue: tiles 0,1 staged; tile0 converted + published
    stage(0, 0); CP_COMMIT;
    stage(1, 1); CP_COMMIT;
    CP_WAIT1;                 // tile0 complete (own copies)
    convertB(0);
    __syncthreads();          // As[0], Bs[0] visible to all

    int sl = 0, sl1 = 1, sl2 = 2;
    for (int kt = 0; kt < KT; kt++) {
        if (kt + 2 < KT) { stage(kt + 2, sl2); CP_COMMIT; }   // depth-2 prefetch
        mmatile(sl);
        if ((kt & 3) == 3) {          // fold group accumulators (NG = 4 k-tiles)
            const int g = kt >> 2;
#pragma unroll
            for (int nj = 0; nj < 4; nj++) {
                float2 s2_ = *(const float2*)(sF + (size_t)g * NTOT + nj * 8);
#pragma unroll
                for (int mi = 0; mi < 2; mi++) {
                    mAcc[mi][nj][0] += gAcc[mi][nj][0] * s2_.x;
                    mAcc[mi][nj][1] += gAcc[mi][nj][1] * s2_.y;
                    mAcc[mi][nj][2] += gAcc[mi][nj][2] * s2_.x;
                    mAcc[mi][nj][3] += gAcc[mi][nj][3] * s2_.y;
                    gAcc[mi][nj][0] = 0.f; gAcc[mi][nj][1] = 0.f;
                    gAcc[mi][nj][2] = 0.f; gAcc[mi][nj][3] = 0.f;
                }
            }
        }
        if (kt + 1 < KT) {
            if (kt + 2 < KT) { CP_WAIT1; } else { CP_WAIT0; }  // tile kt+1 done
            convertB(sl1);             // own data — no barrier needed before
            __syncthreads();           // publish Bs[sl1] + As[sl1] for next iter
        }
        int t = sl; sl = sl1; sl1 = sl2; sl2 = t;
    }

    // epilogue
    if (FC1) {
#pragma unroll
        for (int mi = 0; mi < 2; mi++)
#pragma unroll
            for (int h8 = 0; h8 < 2; h8++) {
                int row = mw * 32 + mi * 16 + (lane >> 2) + h8 * 8;
                int m = m0 + row;
                if (m >= cnt) continue;
                float* orow = g_fc1 + (size_t)(e * NT + m) * NTOT + n0 + nw * 32;
#pragma unroll
                for (int nj = 0; nj < 4; nj++) {
                    float2 v = make_float2(mAcc[mi][nj][h8 * 2 + 0], mAcc[mi][nj][h8 * 2 + 1]);
                    *(float2*)(orow + nj * 8 + (lane & 3) * 2) = v;
                }
            }
    } else {
        const float s2 = s2v[e];
#pragma unroll
        for (int mi = 0; mi < 2; mi++)
#pragma unroll
            for (int h8 = 0; h8 < 2; h8++) {
                int row = mw * 32 + mi * 16 + (lane >> 2) + h8 * 8;
                int m = m0 + row;
                if (m >= cnt) continue;
                int tok = g_ptok[e * NT + m];
                float wgt = g_pgate[e * NT + m] * s2;
                float* od = outp + (size_t)tok * NTOT + n0 + nw * 32;
#pragma unroll
                for (int nj = 0; nj < 4; nj++) {
                    int col = nj * 8 + (lane & 3) * 2;
                    atomicAdd(od + col,     mAcc[mi][nj][h8 * 2 + 0] * wgt);
                    atomicAdd(od + col + 1, mAcc[mi][nj][h8 * 2 + 1] * wgt);
                }
            }
    }
}

// ---------------- silu + qdq(s2): g_fc1 -> g_act2 ----------------
__global__ void __launch_bounds__(256) silu_kernel(const float* __restrict__ s1v,
                                                   const float* __restrict__ s2v) {
    int b = blockIdx.x, e = b >> 8, pos = b & 255;
    if (pos >= g_count[e]) return;
    float s1 = s1v[e], s2 = s2v[e];
    const float* fr = g_fc1 + (size_t)b * (2 * NI);
    __half* orow = g_act2 + (size_t)b * NI;
    for (int j = threadIdx.x * 2; j < NI; j += 512) {
        float2 u2 = *(const float2*)(fr + j);
        float2 g2 = *(const float2*)(fr + NI + j);
        float u0 = u2.x * s1, u1 = u2.y * s1;
        float g0 = g2.x * s1, g1 = g2.y * s1;
        float h0 = u0 * g0 / (1.f + expf(-g0));
        float h1 = u1 * g1 / (1.f + expf(-g1));
        __half2 hq;
        hq.x = qdq_h(h0, s2);
        hq.y = qdq_h(h1, s2);
        *(__half2*)(orow + j) = hq;
    }
}

// ---------------- launch ----------------
extern "C" void kernel_launch(void* const* d_in, const int* in_sizes, int n_in,
                              void* d_out, int out_size) {
    const float* hidden = nullptr;
    const float* logits = nullptr;
    const int*   w1     = nullptr;
    const int*   w2     = nullptr;
    const float* w1s    = nullptr;
    const float* w2s    = nullptr;
    const float* s1     = nullptr;
    const float* s2     = nullptr;

    for (int i = 0; i < n_in; i++) {
        switch (in_sizes[i]) {
            case 524288:    hidden = (const float*)d_in[i]; break;
            case 2048:      logits = (const float*)d_in[i]; break;
            case 184549376: w1     = (const int*)d_in[i];   break;
            case 92274688:  w2     = (const int*)d_in[i];   break;
            case 1441792:   w1s    = (const float*)d_in[i]; break;
            case 720896:    w2s    = (const float*)d_in[i]; break;
            case 8:
                if (!s1) s1 = (const float*)d_in[i];
                else     s2 = (const float*)d_in[i];
                break;
            default: break;
        }
    }
    float* out = (float*)d_out;

    cudaFuncSetAttribute(gemm_core<NH, 2 * NI, true>,
                         cudaFuncAttributeMaxDynamicSharedMemorySize, SMEM_TOTAL);
    cudaFuncSetAttribute(gemm_core<NI, NH, false>,
                         cudaFuncAttributeMaxDynamicSharedMemorySize, SMEM_TOTAL);

    cudaMemsetAsync(out, 0, (size_t)out_size * sizeof(float));
    routing_kernel<<<1, NT>>>(logits);
    act1_kernel<<<NE * NT, 256>>>(hidden, s1);
    gemm_core<NH, 2 * NI, true><<<dim3((2 * NI) / BN, 2, NE), 256, SMEM_TOTAL>>>(w1, w1s, nullptr, nullptr);
    silu_kernel<<<NE * NT, 256>>>(s1, s2);
    gemm_core<NI, NH, false><<<dim3(NH / BN, 2, NE), 256, SMEM_TOTAL>>>(w2, w2s, out, s2);
}